// round 10
// baseline (speedup 1.0000x reference)
#include <cuda_runtime.h>
#include <math.h>
#include <stdint.h>

#define BB 512
#define DD 512
#define LL 24

#define TT  32              // tile is 32x32
#define KC2 32              // k-chunk
#define NCHUNK (DD / KC2)   // 16

// Scratch (device globals — no allocations allowed)
__device__ float        g_dist[BB * BB];
__device__ unsigned int g_lab[BB];
__device__ float        g_sum;
__device__ unsigned int g_cnt;
__device__ unsigned int g_done;

// Packed dual-FP32 FMA (Blackwell f32x2; base-family PTX, sm_100+)
#define FMA2(acc, a, b) \
    asm("fma.rn.f32x2 %0, %1, %2, %0;" : "+l"(acc) : "l"(a), "l"(b))
#define PACK_DUP(out, f) \
    asm("mov.b64 %0, {%1, %1};" : "=l"(out) : "r"(__float_as_uint(f)))
#define UNPACK2(lo, hi, in) \
    asm("mov.b64 {%0, %1}, %2;" : "=r"(lo), "=r"(hi) : "l"(in))

// ---------------------------------------------------------------------------
// Kernel 1: direct distance tiles. 16x16 = 256 blocks x 128 threads (2/SM).
// Full K=512 per tile; row/col norms fused into the staging loads; writes
// dist = sqrt(max(nA + nB - 2G, 0)) straight to g_dist (no partials).
// Microtile: 4 rows (2 packed pairs) x 2 cols -> 4 FFMA2 per kk.
// ---------------------------------------------------------------------------
__global__ __launch_bounds__(128) void k_gram(const float* __restrict__ X,
                                              const int* __restrict__ labels) {
    __shared__ float As[2][KC2][TT + 4];
    __shared__ float Bs[2][KC2][TT + 4];
    __shared__ float normA[TT];
    __shared__ float normB[TT];

    int tid = threadIdx.x;

    if (blockIdx.x == 0 && blockIdx.y == 0) {
        for (int i = tid; i < BB; i += 128) {
            unsigned m = 0u;
#pragma unroll
            for (int l = 0; l < LL; ++l)
                if (labels[i * LL + l] != 0) m |= (1u << l);
            g_lab[i] = m;
        }
        if (tid == 0) { g_sum = 0.0f; g_cnt = 0u; g_done = 0u; }
    }
    if (tid < TT) { normA[tid] = 0.0f; normB[tid] = 0.0f; }

    int rowBase = blockIdx.y * TT;
    int colBase = blockIdx.x * TT;
    int ty = tid >> 4;          // 0..7  : rows ty*4 .. ty*4+3 (2 pairs)
    int tx = tid & 15;          // 0..15 : cols tx*2, tx*2+1

    // staging coords: 2 float4 per tile per thread
    int r0 = tid >> 3;                  // 0..15
    int r1 = r0 + 16;                   // 16..31
    int kg = (tid & 7) * 4;             // 0..28
    const float* Arow0 = &X[(rowBase + r0) * DD];
    const float* Arow1 = &X[(rowBase + r1) * DD];
    const float* Brow0 = &X[(colBase + r0) * DD];
    const float* Brow1 = &X[(colBase + r1) * DD];

    unsigned long long acc[2][2] = {{0ull, 0ull}, {0ull, 0ull}};
    float na0 = 0.0f, na1 = 0.0f, nb0 = 0.0f, nb1 = 0.0f;

    // preload chunk 0
    float4 pa0 = *reinterpret_cast<const float4*>(&Arow0[kg]);
    float4 pa1 = *reinterpret_cast<const float4*>(&Arow1[kg]);
    float4 pb0 = *reinterpret_cast<const float4*>(&Brow0[kg]);
    float4 pb1 = *reinterpret_cast<const float4*>(&Brow1[kg]);

#pragma unroll 1
    for (int c = 0; c < NCHUNK; ++c) {
        int buf = c & 1;
        As[buf][kg + 0][r0] = pa0.x; As[buf][kg + 1][r0] = pa0.y;
        As[buf][kg + 2][r0] = pa0.z; As[buf][kg + 3][r0] = pa0.w;
        As[buf][kg + 0][r1] = pa1.x; As[buf][kg + 1][r1] = pa1.y;
        As[buf][kg + 2][r1] = pa1.z; As[buf][kg + 3][r1] = pa1.w;
        Bs[buf][kg + 0][r0] = pb0.x; Bs[buf][kg + 1][r0] = pb0.y;
        Bs[buf][kg + 2][r0] = pb0.z; Bs[buf][kg + 3][r0] = pb0.w;
        Bs[buf][kg + 0][r1] = pb1.x; Bs[buf][kg + 1][r1] = pb1.y;
        Bs[buf][kg + 2][r1] = pb1.z; Bs[buf][kg + 3][r1] = pb1.w;
        // fused norm partials (reuse staged registers, no extra loads)
        na0 += pa0.x*pa0.x + pa0.y*pa0.y + pa0.z*pa0.z + pa0.w*pa0.w;
        na1 += pa1.x*pa1.x + pa1.y*pa1.y + pa1.z*pa1.z + pa1.w*pa1.w;
        nb0 += pb0.x*pb0.x + pb0.y*pb0.y + pb0.z*pb0.z + pb0.w*pb0.w;
        nb1 += pb1.x*pb1.x + pb1.y*pb1.y + pb1.z*pb1.z + pb1.w*pb1.w;
        __syncthreads();

        if (c + 1 < NCHUNK) {
            int ko = (c + 1) * KC2;
            pa0 = *reinterpret_cast<const float4*>(&Arow0[ko + kg]);
            pa1 = *reinterpret_cast<const float4*>(&Arow1[ko + kg]);
            pb0 = *reinterpret_cast<const float4*>(&Brow0[ko + kg]);
            pb1 = *reinterpret_cast<const float4*>(&Brow1[ko + kg]);
        }

#pragma unroll
        for (int kk = 0; kk < KC2; ++kk) {
            ulonglong2 a01 =
                *reinterpret_cast<const ulonglong2*>(&As[buf][kk][ty * 4]);
            float2 b2 = *reinterpret_cast<const float2*>(&Bs[buf][kk][tx * 2]);
            unsigned long long B0, B1;
            PACK_DUP(B0, b2.x); PACK_DUP(B1, b2.y);
            FMA2(acc[0][0], a01.x, B0); FMA2(acc[0][1], a01.x, B1);
            FMA2(acc[1][0], a01.y, B0); FMA2(acc[1][1], a01.y, B1);
        }
        __syncthreads();
    }

    // combine norm partials (8 threads per row)
    atomicAdd(&normA[r0], na0);
    atomicAdd(&normA[r1], na1);
    atomicAdd(&normB[r0], nb0);
    atomicAdd(&normB[r1], nb1);
    __syncthreads();

    // epilogue: dist = sqrt(max(nA + nB - 2G, 0))
    float nB0 = normB[tx * 2 + 0];
    float nB1 = normB[tx * 2 + 1];
#pragma unroll
    for (int p = 0; p < 2; ++p) {
        unsigned lo0, hi0, lo1, hi1;
        UNPACK2(lo0, hi0, acc[p][0]);
        UNPACK2(lo1, hi1, acc[p][1]);
        int rl = ty * 4 + p * 2;
        float nAl = normA[rl], nAh = normA[rl + 1];
        float sql0 = nAl + nB0 - 2.0f * __uint_as_float(lo0);
        float sql1 = nAl + nB1 - 2.0f * __uint_as_float(lo1);
        float sqh0 = nAh + nB0 - 2.0f * __uint_as_float(hi0);
        float sqh1 = nAh + nB1 - 2.0f * __uint_as_float(hi1);
        float2 dl = make_float2(sql0 > 0.0f ? sqrtf(sql0) : 0.0f,
                                sql1 > 0.0f ? sqrtf(sql1) : 0.0f);
        float2 dh = make_float2(sqh0 > 0.0f ? sqrtf(sqh0) : 0.0f,
                                sqh1 > 0.0f ? sqrtf(sqh1) : 0.0f);
        *reinterpret_cast<float2*>(
            &g_dist[(rowBase + rl) * BB + colBase + tx * 2]) = dl;
        *reinterpret_cast<float2*>(
            &g_dist[(rowBase + rl + 1) * BB + colBase + tx * 2]) = dh;
    }
}

// ---------------------------------------------------------------------------
// Kernel 2: triplets. 512 blocks (1 anchor) x 128 threads, ballot compaction.
// Reads final g_dist directly (1 load per distance).
// ---------------------------------------------------------------------------
__global__ __launch_bounds__(128) void k_tri(float* __restrict__ out) {
    __shared__ float    nd[BB];
    __shared__ int      nn;
    __shared__ float    wsum[4];
    __shared__ unsigned wcnt[4];

    int i    = blockIdx.x;
    int tid  = threadIdx.x;
    int lane = tid & 31;
    int wid  = tid >> 5;

    unsigned mi = g_lab[i];
    if (tid == 0) nn = 0;

    float dv[4];
    int   pf[4];
#pragma unroll
    for (int s = 0; s < 4; ++s) {
        int j = s * 128 + tid;
        dv[s] = g_dist[i * BB + j];
        pf[s] = (g_lab[j] & mi) != 0u;
    }
    __syncthreads();

#pragma unroll
    for (int s = 0; s < 4; ++s) {
        unsigned bal = __ballot_sync(0xffffffffu, !pf[s]);
        if (bal) {
            int base = 0;
            if (lane == 0) base = atomicAdd(&nn, __popc(bal));
            base = __shfl_sync(0xffffffffu, base, 0);
            if (!pf[s]) {
                int r = __popc(bal & ((1u << lane) - 1u));
                nd[base + r] = dv[s];
            }
        }
    }
    __syncthreads();

    int N = nn;
    float    lsum = 0.0f;
    unsigned lcnt = 0u;
    if (N > 0) {
#pragma unroll
        for (int s = 0; s < 4; ++s) {
            if (pf[s]) {
                float dj = dv[s];
                for (int k = 0; k < N; ++k) {
                    float v = dj - nd[k];
                    if (v > 1e-16f) { lsum += v; lcnt++; }
                }
            }
        }
    }

#pragma unroll
    for (int off = 16; off; off >>= 1) {
        lsum += __shfl_down_sync(0xffffffffu, lsum, off);
        lcnt += __shfl_down_sync(0xffffffffu, lcnt, off);
    }
    if (lane == 0) { wsum[wid] = lsum; wcnt[wid] = lcnt; }
    __syncthreads();
    if (wid == 0) {
        lsum = (lane < 4) ? wsum[lane] : 0.0f;
        lcnt = (lane < 4) ? wcnt[lane] : 0u;
#pragma unroll
        for (int off = 2; off; off >>= 1) {
            lsum += __shfl_down_sync(0xffffffffu, lsum, off);
            lcnt += __shfl_down_sync(0xffffffffu, lcnt, off);
        }
        if (lane == 0) {
            if (lcnt != 0u || lsum != 0.0f) {
                atomicAdd(&g_sum, lsum);
                atomicAdd(&g_cnt, lcnt);
            }
            __threadfence();
            unsigned prev = atomicAdd(&g_done, 1u);
            if (prev == (unsigned)(BB - 1)) {
                float    s = *((volatile float*)&g_sum);
                unsigned c = *((volatile unsigned*)&g_cnt);
                out[0] = (float)((double)s / ((double)c + 1e-16));
                g_sum = 0.0f; g_cnt = 0u; g_done = 0u;  // reset for replay
            }
        }
    }
}

extern "C" void kernel_launch(void* const* d_in, const int* in_sizes, int n_in,
                              void* d_out, int out_size) {
    const float* src = (const float*)d_in[0];  // (B, D) float32
    const int*   lab = (const int*)d_in[1];    // (B, L) int32

    dim3 grid(BB / TT, BB / TT);               // 16 x 16 = 256 blocks
    k_gram<<<grid, 128>>>(src, lab);
    k_tri<<<BB, 128>>>((float*)d_out);
}

// round 11
// speedup vs baseline: 1.1471x; 1.1471x over previous
#include <cuda_runtime.h>
#include <math.h>
#include <stdint.h>

#define BB 512
#define DD 512
#define LL 24

#define TILE 64
#define KC   16
#define SPLITS 4
#define KSP (DD / SPLITS)   // 128
#define NCHUNK (KSP / KC)   // 8
#define NBLK 256            // 8 x 8 tiles x 4 K-splits

// Scratch (device globals — no allocations allowed)
__device__ float             g_part[SPLITS][BB * BB];
__device__ float             g_npart[SPLITS][BB];
__device__ unsigned int      g_lab[BB];
__device__ float             g_sum;
__device__ unsigned int      g_cnt;
__device__ unsigned int      g_done;
__device__ volatile unsigned g_bar;

// Packed dual-FP32 FMA (Blackwell f32x2; base-family PTX, sm_100+)
#define FMA2(acc, a, b) \
    asm("fma.rn.f32x2 %0, %1, %2, %0;" : "+l"(acc) : "l"(a), "l"(b))
#define PACK_DUP(out, f) \
    asm("mov.b64 %0, {%1, %1};" : "=l"(out) : "r"(__float_as_uint(f)))
#define UNPACK2(lo, hi, in) \
    asm("mov.b64 {%0, %1}, %2;" : "=r"(lo), "=r"(hi) : "l"(in))

// ---------------------------------------------------------------------------
// Fused kernel: round-7 gram (64x64 tile, K-split 4, 256 blocks x 128 thr,
// 2 CTA/SM) -> grid spin barrier (all 256 co-resident: 296 slots) ->
// round-7 triplet phase (2 anchors per block) -> finalize in last block.
// ---------------------------------------------------------------------------
__global__ __launch_bounds__(128) void k_fused(const float* __restrict__ X,
                                               const int* __restrict__ labels,
                                               float* __restrict__ out) {
    __shared__ float As[2][KC][TILE + 4];
    __shared__ float Bs[2][KC][TILE + 4];
    __shared__ float    nd[BB];
    __shared__ int      nn;
    __shared__ float    wsum[4];
    __shared__ unsigned wcnt[4];

    int tid = threadIdx.x;
    int wu  = blockIdx.x;

    if (wu == 0) {
        for (int i = tid; i < BB; i += 128) {
            unsigned m = 0u;
#pragma unroll
            for (int l = 0; l < LL; ++l)
                if (labels[i * LL + l] != 0) m |= (1u << l);
            g_lab[i] = m;
        }
    }

    // ---------------- Phase 1: Gram partial tile (round-7 verbatim) ---------
    int bx = wu & 7;
    int by = (wu >> 3) & 7;
    int z  = wu >> 6;
    int ty = tid >> 4;          // 0..7  : 8 rows (4 pairs)
    int tx = tid & 15;          // 0..15 : 4 cols
    int rowBase = by * TILE;
    int colBase = bx * TILE;
    int kBase   = z * KSP;

    int sr0 = tid >> 2,           sk0 = (tid & 3) * 4;
    int sr1 = (tid + 128) >> 2;
    const float* Arow0 = &X[(rowBase + sr0) * DD + kBase];
    const float* Arow1 = &X[(rowBase + sr1) * DD + kBase];
    const float* Brow0 = &X[(colBase + sr0) * DD + kBase];
    const float* Brow1 = &X[(colBase + sr1) * DD + kBase];

    unsigned long long acc[4][4];
#pragma unroll
    for (int p = 0; p < 4; ++p)
#pragma unroll
        for (int c = 0; c < 4; ++c) acc[p][c] = 0ull;

    float4 pa0 = *reinterpret_cast<const float4*>(&Arow0[sk0]);
    float4 pa1 = *reinterpret_cast<const float4*>(&Arow1[sk0]);
    float4 pb0 = *reinterpret_cast<const float4*>(&Brow0[sk0]);
    float4 pb1 = *reinterpret_cast<const float4*>(&Brow1[sk0]);

#pragma unroll
    for (int c = 0; c < NCHUNK; ++c) {
        int buf = c & 1;
        As[buf][sk0 + 0][sr0] = pa0.x; As[buf][sk0 + 1][sr0] = pa0.y;
        As[buf][sk0 + 2][sr0] = pa0.z; As[buf][sk0 + 3][sr0] = pa0.w;
        As[buf][sk0 + 0][sr1] = pa1.x; As[buf][sk0 + 1][sr1] = pa1.y;
        As[buf][sk0 + 2][sr1] = pa1.z; As[buf][sk0 + 3][sr1] = pa1.w;
        Bs[buf][sk0 + 0][sr0] = pb0.x; Bs[buf][sk0 + 1][sr0] = pb0.y;
        Bs[buf][sk0 + 2][sr0] = pb0.z; Bs[buf][sk0 + 3][sr0] = pb0.w;
        Bs[buf][sk0 + 0][sr1] = pb1.x; Bs[buf][sk0 + 1][sr1] = pb1.y;
        Bs[buf][sk0 + 2][sr1] = pb1.z; Bs[buf][sk0 + 3][sr1] = pb1.w;
        __syncthreads();

        if (c + 1 < NCHUNK) {
            int ko = (c + 1) * KC;
            pa0 = *reinterpret_cast<const float4*>(&Arow0[ko + sk0]);
            pa1 = *reinterpret_cast<const float4*>(&Arow1[ko + sk0]);
            pb0 = *reinterpret_cast<const float4*>(&Brow0[ko + sk0]);
            pb1 = *reinterpret_cast<const float4*>(&Brow1[ko + sk0]);
        }

#pragma unroll
        for (int kk = 0; kk < KC; ++kk) {
            const ulonglong2* ap =
                reinterpret_cast<const ulonglong2*>(&As[buf][kk][ty * 8]);
            ulonglong2 a01 = ap[0];
            ulonglong2 a23 = ap[1];
            float4 b4 = *reinterpret_cast<const float4*>(&Bs[buf][kk][tx * 4]);
            unsigned long long B0, B1, B2, B3;
            PACK_DUP(B0, b4.x); PACK_DUP(B1, b4.y);
            PACK_DUP(B2, b4.z); PACK_DUP(B3, b4.w);
            FMA2(acc[0][0], a01.x, B0); FMA2(acc[0][1], a01.x, B1);
            FMA2(acc[0][2], a01.x, B2); FMA2(acc[0][3], a01.x, B3);
            FMA2(acc[1][0], a01.y, B0); FMA2(acc[1][1], a01.y, B1);
            FMA2(acc[1][2], a01.y, B2); FMA2(acc[1][3], a01.y, B3);
            FMA2(acc[2][0], a23.x, B0); FMA2(acc[2][1], a23.x, B1);
            FMA2(acc[2][2], a23.x, B2); FMA2(acc[2][3], a23.x, B3);
            FMA2(acc[3][0], a23.y, B0); FMA2(acc[3][1], a23.y, B1);
            FMA2(acc[3][2], a23.y, B2); FMA2(acc[3][3], a23.y, B3);
        }
        __syncthreads();
    }

    int gj = colBase + tx * 4;
#pragma unroll
    for (int p = 0; p < 4; ++p) {
        unsigned lo[4], hi[4];
#pragma unroll
        for (int c = 0; c < 4; ++c) UNPACK2(lo[c], hi[c], acc[p][c]);
        int gi0 = rowBase + ty * 8 + p * 2;
        float4 r0 = make_float4(__uint_as_float(lo[0]), __uint_as_float(lo[1]),
                                __uint_as_float(lo[2]), __uint_as_float(lo[3]));
        float4 r1 = make_float4(__uint_as_float(hi[0]), __uint_as_float(hi[1]),
                                __uint_as_float(hi[2]), __uint_as_float(hi[3]));
        *reinterpret_cast<float4*>(&g_part[z][gi0 * BB + gj])       = r0;
        *reinterpret_cast<float4*>(&g_part[z][(gi0 + 1) * BB + gj]) = r1;
        int d0 = gi0 - gj;
        if ((unsigned)d0 < 4u) g_npart[z][gi0] = (&r0.x)[d0];
        int d1 = gi0 + 1 - gj;
        if ((unsigned)d1 < 4u) g_npart[z][gi0 + 1] = (&r1.x)[d1];
    }

    // ---------------- Grid barrier (all 256 blocks co-resident) -------------
    __threadfence();
    __syncthreads();
    if (tid == 0) {
        atomicAdd((unsigned*)&g_bar, 1u);
        while (g_bar < NBLK) { }
    }
    __syncthreads();

    // ---------------- Phase 2: triplets, 2 anchors per block ----------------
    int lane = tid & 31;
    int wid  = tid >> 5;
    float    lsum = 0.0f;
    unsigned lcnt = 0u;

    for (int a = 0; a < 2; ++a) {
        int i = blockIdx.x * 2 + a;
        unsigned mi = g_lab[i];
        const float* qi = &g_npart[0][i];
        float ni = ((qi[0] + qi[BB]) + qi[2 * BB]) + qi[3 * BB];
        if (tid == 0) nn = 0;

        float dv[4];
        int   pf[4];
#pragma unroll
        for (int s = 0; s < 4; ++s) {
            int j = s * 128 + tid;
            const float* p = &g_part[0][i * BB + j];
            float G  = ((p[0] + p[BB * BB]) + p[2 * BB * BB]) + p[3 * BB * BB];
            const float* q = &g_npart[0][j];
            float nj = ((q[0] + q[BB]) + q[2 * BB]) + q[3 * BB];
            float sq = ni + nj - 2.0f * G;
            dv[s] = (sq > 0.0f) ? sqrtf(sq) : 0.0f;
            pf[s] = (g_lab[j] & mi) != 0u;
        }
        __syncthreads();

#pragma unroll
        for (int s = 0; s < 4; ++s) {
            unsigned bal = __ballot_sync(0xffffffffu, !pf[s]);
            if (bal) {
                int base = 0;
                if (lane == 0) base = atomicAdd(&nn, __popc(bal));
                base = __shfl_sync(0xffffffffu, base, 0);
                if (!pf[s]) {
                    int r = __popc(bal & ((1u << lane) - 1u));
                    nd[base + r] = dv[s];
                }
            }
        }
        __syncthreads();

        int N = nn;
        if (N > 0) {
#pragma unroll
            for (int s = 0; s < 4; ++s) {
                if (pf[s]) {
                    float dj = dv[s];
                    for (int k = 0; k < N; ++k) {
                        float v = dj - nd[k];
                        if (v > 1e-16f) { lsum += v; lcnt++; }
                    }
                }
            }
        }
        __syncthreads();
    }

    // ---------------- Reduce + accumulate + finalize ------------------------
#pragma unroll
    for (int off = 16; off; off >>= 1) {
        lsum += __shfl_down_sync(0xffffffffu, lsum, off);
        lcnt += __shfl_down_sync(0xffffffffu, lcnt, off);
    }
    if (lane == 0) { wsum[wid] = lsum; wcnt[wid] = lcnt; }
    __syncthreads();
    if (wid == 0) {
        lsum = (lane < 4) ? wsum[lane] : 0.0f;
        lcnt = (lane < 4) ? wcnt[lane] : 0u;
#pragma unroll
        for (int off = 2; off; off >>= 1) {
            lsum += __shfl_down_sync(0xffffffffu, lsum, off);
            lcnt += __shfl_down_sync(0xffffffffu, lcnt, off);
        }
        if (lane == 0) {
            if (lcnt != 0u || lsum != 0.0f) {
                atomicAdd(&g_sum, lsum);
                atomicAdd(&g_cnt, lcnt);
            }
            __threadfence();
            unsigned prev = atomicAdd(&g_done, 1u);
            if (prev == NBLK - 1) {
                float    s = *((volatile float*)&g_sum);
                unsigned c = *((volatile unsigned*)&g_cnt);
                out[0] = (float)((double)s / ((double)c + 1e-16));
                g_sum = 0.0f; g_cnt = 0u; g_done = 0u; g_bar = 0u;  // replay reset
            }
        }
    }
}

extern "C" void kernel_launch(void* const* d_in, const int* in_sizes, int n_in,
                              void* d_out, int out_size) {
    const float* src = (const float*)d_in[0];  // (B, D) float32
    const int*   lab = (const int*)d_in[1];    // (B, L) int32

    k_fused<<<NBLK, 128>>>(src, lab, (float*)d_out);
}

// round 13
// speedup vs baseline: 1.3191x; 1.1500x over previous
#include <cuda_runtime.h>
#include <math.h>
#include <stdint.h>

#define BB 512
#define DD 512
#define LL 24

#define TILE 64
#define KC   16
#define SPLITS 4
#define KSP (DD / SPLITS)   // 128
#define NCHUNK (KSP / KC)   // 8

// Scratch (device globals — no allocations allowed)
__device__ float        g_part[SPLITS][BB * BB];
__device__ float        g_npart[SPLITS][BB];
__device__ unsigned int g_lab[BB];
__device__ float        g_sum;
__device__ unsigned int g_cnt;
__device__ unsigned int g_done;

// Packed dual-FP32 FMA (Blackwell f32x2 path; base-family PTX, sm_100+)
#define FMA2(acc, a, b) \
    asm("fma.rn.f32x2 %0, %1, %2, %0;" : "+l"(acc) : "l"(a), "l"(b))
#define PACK_DUP(out, f) \
    asm("mov.b64 %0, {%1, %1};" : "=l"(out) : "r"(__float_as_uint(f)))
#define UNPACK2(lo, hi, in) \
    asm("mov.b64 {%0, %1}, %2;" : "=r"(lo), "=r"(hi) : "l"(in))

// ---------------------------------------------------------------------------
// Kernel 1: Gram partials (round-7 geometry). 64x64 tile, K-split 4 ->
// 256 blocks x 128 threads (2 CTA/SM). Microtile 8 rows (4 pairs) x 4 cols =
// 16 FFMA2 per kk. Chunk loop NOT unrolled: mainloop body ~6 KB, fits L0 I$
// (fully unrolled it was ~47 KB -> I$ L2 tier).
// ---------------------------------------------------------------------------
__global__ __launch_bounds__(128) void k_gram(const float* __restrict__ X,
                                              const int* __restrict__ labels) {
    __shared__ float As[2][KC][TILE + 4];
    __shared__ float Bs[2][KC][TILE + 4];

    int tid = threadIdx.x;

    if (blockIdx.x == 0 && blockIdx.y == 0 && blockIdx.z == 0) {
        for (int i = tid; i < BB; i += 128) {
            unsigned m = 0u;
#pragma unroll
            for (int l = 0; l < LL; ++l)
                if (labels[i * LL + l] != 0) m |= (1u << l);
            g_lab[i] = m;
        }
        if (tid == 0) { g_sum = 0.0f; g_cnt = 0u; g_done = 0u; }
    }

    int ty = tid >> 4;          // 0..7  : 8 rows (4 pairs)
    int tx = tid & 15;          // 0..15 : 4 cols
    int rowBase = blockIdx.y * TILE;
    int colBase = blockIdx.x * TILE;
    int z       = blockIdx.z;
    int kBase   = z * KSP;

    // staging coords: 2 float4 per tile per thread
    int sr0 = tid >> 2,           sk0 = (tid & 3) * 4;
    int sr1 = sr0 + 32;
    const float* Arow0 = &X[(rowBase + sr0) * DD + kBase];
    const float* Arow1 = &X[(rowBase + sr1) * DD + kBase];
    const float* Brow0 = &X[(colBase + sr0) * DD + kBase];
    const float* Brow1 = &X[(colBase + sr1) * DD + kBase];

    unsigned long long acc[4][4];
#pragma unroll
    for (int p = 0; p < 4; ++p)
#pragma unroll
        for (int c = 0; c < 4; ++c) acc[p][c] = 0ull;

    // preload chunk 0
    float4 pa0 = *reinterpret_cast<const float4*>(&Arow0[sk0]);
    float4 pa1 = *reinterpret_cast<const float4*>(&Arow1[sk0]);
    float4 pb0 = *reinterpret_cast<const float4*>(&Brow0[sk0]);
    float4 pb1 = *reinterpret_cast<const float4*>(&Brow1[sk0]);

#pragma unroll 1
    for (int c = 0; c < NCHUNK; ++c) {
        int buf = c & 1;
        As[buf][sk0 + 0][sr0] = pa0.x; As[buf][sk0 + 1][sr0] = pa0.y;
        As[buf][sk0 + 2][sr0] = pa0.z; As[buf][sk0 + 3][sr0] = pa0.w;
        As[buf][sk0 + 0][sr1] = pa1.x; As[buf][sk0 + 1][sr1] = pa1.y;
        As[buf][sk0 + 2][sr1] = pa1.z; As[buf][sk0 + 3][sr1] = pa1.w;
        Bs[buf][sk0 + 0][sr0] = pb0.x; Bs[buf][sk0 + 1][sr0] = pb0.y;
        Bs[buf][sk0 + 2][sr0] = pb0.z; Bs[buf][sk0 + 3][sr0] = pb0.w;
        Bs[buf][sk0 + 0][sr1] = pb1.x; Bs[buf][sk0 + 1][sr1] = pb1.y;
        Bs[buf][sk0 + 2][sr1] = pb1.z; Bs[buf][sk0 + 3][sr1] = pb1.w;
        __syncthreads();

        // issue next chunk's loads (overlap with FMA below)
        if (c + 1 < NCHUNK) {
            int ko = (c + 1) * KC;
            pa0 = *reinterpret_cast<const float4*>(&Arow0[ko + sk0]);
            pa1 = *reinterpret_cast<const float4*>(&Arow1[ko + sk0]);
            pb0 = *reinterpret_cast<const float4*>(&Brow0[ko + sk0]);
            pb1 = *reinterpret_cast<const float4*>(&Brow1[ko + sk0]);
        }

#pragma unroll
        for (int kk = 0; kk < KC; ++kk) {
            const ulonglong2* ap =
                reinterpret_cast<const ulonglong2*>(&As[buf][kk][ty * 8]);
            ulonglong2 a01 = ap[0];
            ulonglong2 a23 = ap[1];
            float4 b4 = *reinterpret_cast<const float4*>(&Bs[buf][kk][tx * 4]);
            unsigned long long B0, B1, B2, B3;
            PACK_DUP(B0, b4.x); PACK_DUP(B1, b4.y);
            PACK_DUP(B2, b4.z); PACK_DUP(B3, b4.w);
            FMA2(acc[0][0], a01.x, B0); FMA2(acc[0][1], a01.x, B1);
            FMA2(acc[0][2], a01.x, B2); FMA2(acc[0][3], a01.x, B3);
            FMA2(acc[1][0], a01.y, B0); FMA2(acc[1][1], a01.y, B1);
            FMA2(acc[1][2], a01.y, B2); FMA2(acc[1][3], a01.y, B3);
            FMA2(acc[2][0], a23.x, B0); FMA2(acc[2][1], a23.x, B1);
            FMA2(acc[2][2], a23.x, B2); FMA2(acc[2][3], a23.x, B3);
            FMA2(acc[3][0], a23.y, B0); FMA2(acc[3][1], a23.y, B1);
            FMA2(acc[3][2], a23.y, B2); FMA2(acc[3][3], a23.y, B3);
        }
        __syncthreads();
    }

    // epilogue: 4 row-pairs x 4 cols -> two float4 stores per pair
    int gj = colBase + tx * 4;
#pragma unroll
    for (int p = 0; p < 4; ++p) {
        unsigned lo[4], hi[4];
#pragma unroll
        for (int c = 0; c < 4; ++c) UNPACK2(lo[c], hi[c], acc[p][c]);
        int gi0 = rowBase + ty * 8 + p * 2;
        float4 r0 = make_float4(__uint_as_float(lo[0]), __uint_as_float(lo[1]),
                                __uint_as_float(lo[2]), __uint_as_float(lo[3]));
        float4 r1 = make_float4(__uint_as_float(hi[0]), __uint_as_float(hi[1]),
                                __uint_as_float(hi[2]), __uint_as_float(hi[3]));
        *reinterpret_cast<float4*>(&g_part[z][gi0 * BB + gj])       = r0;
        *reinterpret_cast<float4*>(&g_part[z][(gi0 + 1) * BB + gj]) = r1;
        int d0 = gi0 - gj;
        if ((unsigned)d0 < 4u) g_npart[z][gi0] = (&r0.x)[d0];
        int d1 = gi0 + 1 - gj;
        if ((unsigned)d1 < 4u) g_npart[z][gi0 + 1] = (&r1.x)[d1];
    }
}

// ---------------------------------------------------------------------------
// Kernel 2: triplets. 512 blocks (1 anchor) x 128 threads, ballot compaction.
// ---------------------------------------------------------------------------
__global__ __launch_bounds__(128) void k_tri(float* __restrict__ out) {
    __shared__ float    nd[BB];
    __shared__ int      nn;
    __shared__ float    wsum[4];
    __shared__ unsigned wcnt[4];

    int i    = blockIdx.x;
    int tid  = threadIdx.x;
    int lane = tid & 31;
    int wid  = tid >> 5;

    unsigned mi = g_lab[i];
    const float* qi = &g_npart[0][i];
    float ni = ((qi[0] + qi[BB]) + qi[2 * BB]) + qi[3 * BB];
    if (tid == 0) nn = 0;

    float dv[4];
    int   pf[4];
#pragma unroll
    for (int s = 0; s < 4; ++s) {
        int j = s * 128 + tid;
        const float* p = &g_part[0][i * BB + j];
        float G  = ((p[0] + p[BB * BB]) + p[2 * BB * BB]) + p[3 * BB * BB];
        const float* q = &g_npart[0][j];
        float nj = ((q[0] + q[BB]) + q[2 * BB]) + q[3 * BB];
        float sq = ni + nj - 2.0f * G;
        dv[s] = (sq > 0.0f) ? sqrtf(sq) : 0.0f;
        pf[s] = (g_lab[j] & mi) != 0u;
    }
    __syncthreads();

#pragma unroll
    for (int s = 0; s < 4; ++s) {
        unsigned bal = __ballot_sync(0xffffffffu, !pf[s]);
        if (bal) {
            int base = 0;
            if (lane == 0) base = atomicAdd(&nn, __popc(bal));
            base = __shfl_sync(0xffffffffu, base, 0);
            if (!pf[s]) {
                int r = __popc(bal & ((1u << lane) - 1u));
                nd[base + r] = dv[s];
            }
        }
    }
    __syncthreads();

    int N = nn;
    float    lsum = 0.0f;
    unsigned lcnt = 0u;
    if (N > 0) {
#pragma unroll
        for (int s = 0; s < 4; ++s) {
            if (pf[s]) {
                float dj = dv[s];
                for (int k = 0; k < N; ++k) {
                    float v = dj - nd[k];
                    if (v > 1e-16f) { lsum += v; lcnt++; }
                }
            }
        }
    }

#pragma unroll
    for (int off = 16; off; off >>= 1) {
        lsum += __shfl_down_sync(0xffffffffu, lsum, off);
        lcnt += __shfl_down_sync(0xffffffffu, lcnt, off);
    }
    if (lane == 0) { wsum[wid] = lsum; wcnt[wid] = lcnt; }
    __syncthreads();
    if (wid == 0) {
        lsum = (lane < 4) ? wsum[lane] : 0.0f;
        lcnt = (lane < 4) ? wcnt[lane] : 0u;
#pragma unroll
        for (int off = 2; off; off >>= 1) {
            lsum += __shfl_down_sync(0xffffffffu, lsum, off);
            lcnt += __shfl_down_sync(0xffffffffu, lcnt, off);
        }
        if (lane == 0) {
            if (lcnt != 0u || lsum != 0.0f) {
                atomicAdd(&g_sum, lsum);
                atomicAdd(&g_cnt, lcnt);
            }
            __threadfence();
            unsigned prev = atomicAdd(&g_done, 1u);
            if (prev == (unsigned)(BB - 1)) {
                float    s = *((volatile float*)&g_sum);
                unsigned c = *((volatile unsigned*)&g_cnt);
                out[0] = (float)((double)s / ((double)c + 1e-16));
                g_sum = 0.0f; g_cnt = 0u; g_done = 0u;  // reset for replay
            }
        }
    }
}

extern "C" void kernel_launch(void* const* d_in, const int* in_sizes, int n_in,
                              void* d_out, int out_size) {
    const float* src = (const float*)d_in[0];  // (B, D) float32
    const int*   lab = (const int*)d_in[1];    // (B, L) int32

    dim3 grid(BB / TILE, BB / TILE, SPLITS);   // 8 x 8 x 4 = 256 blocks
    k_gram<<<grid, 128>>>(src, lab);
    k_tri<<<BB, 128>>>((float*)d_out);
}